// round 9
// baseline (speedup 1.0000x reference)
#include <cuda_runtime.h>
#include <math.h>

#define D_MODEL 2048
#define NUM_HEADS 16
#define HEAD_DIM 128
#define MAX_SEQ_LEN 32768
#define NBLK 736                    // 16 heads x 46 tiles; <= 5 CTA/SM x 148 SMs
#define KB2 46                      // attention tiles per head
#define SCALE 0.08838834764831845f  // 1/sqrt(128)

// ---------------- device scratch (no allocations allowed) ----------------
__device__ float g_q[D_MODEL];
__device__ float g_k[D_MODEL];
__device__ float g_v[D_MODEL];
__device__ float g_attn[D_MODEL];
__device__ float g_pm[NUM_HEADS * KB2];
__device__ float g_pl[NUM_HEADS * KB2];
__device__ float g_pacc[NUM_HEADS * KB2 * HEAD_DIM];
__device__ unsigned g_qkv_cnt;          // zero-init; reset by last done block
__device__ unsigned g_attn_cnt;         // zero-init; reset by last done block
__device__ unsigned g_done_cnt;         // zero-init; reset by last done block
__device__ unsigned g_sem[NUM_HEADS];   // self-resetting per-head semaphore

// ============================================================================
// SINGLE persistent kernel. 736 blocks of 256 threads, all resident
// (launch_bounds(256,5) forces regs<=48 => 5 CTAs/SM; 736 <= 740).
// Phase A: QKV matvecs (release g_qkv_cnt)
// Phase B: upper-half cache copy (independent of A; hides A's tail + spin)
// Phase C: acquire; lower-half copy + flash attention; per-head reduce
//          (reducers release g_attn_cnt)
// Phase D: acquire; output projection y = attn @ Wo.T
// ============================================================================
__global__ __launch_bounds__(256, 5) void mega_kernel(
        const float* __restrict__ x,
        const float* __restrict__ Wq,
        const float* __restrict__ Wk,
        const float* __restrict__ Wv,
        const float* __restrict__ Wo,
        const float4* __restrict__ pk,
        const float4* __restrict__ pv,
        float4* __restrict__ ok,
        float4* __restrict__ ov,
        const int* __restrict__ ci_p,
        float* __restrict__ y) {
    __shared__ float xs[D_MODEL];
    __shared__ float wm[8], wl[8];
    __shared__ float wacc[8][HEAD_DIM];
    __shared__ bool is_last;

    int tid = threadIdx.x, wid = tid >> 5, lane = tid & 31;
    int bid = blockIdx.x;

    // ---- load x (8KB, L2-broadcast across blocks) ----
    {
        float4* xs4 = (float4*)xs;
        const float4* x4 = (const float4*)x;
#pragma unroll
        for (int i = 0; i < 2; i++) xs4[tid + i * 256] = x4[tid + i * 256];
    }
    __syncthreads();

    // ---- Phase A: QKV matvecs, warp per row, strided over 6144 rows ----
    for (int grow = bid * 8 + wid; grow < 3 * D_MODEL; grow += NBLK * 8) {
        int mat = grow >> 11;
        int row = grow & 2047;
        const float* W = (mat == 0) ? Wq : ((mat == 1) ? Wk : Wv);
        const float4* wr = (const float4*)(W + (size_t)row * D_MODEL);
        float acc = 0.f;
#pragma unroll
        for (int b = 0; b < 4; b++) {
            float4 w[4];
#pragma unroll
            for (int i = 0; i < 4; i++) w[i] = __ldcs(wr + lane + (b * 4 + i) * 32);
#pragma unroll
            for (int i = 0; i < 4; i++) {
                int j = lane + (b * 4 + i) * 32;
                acc += xs[j * 4 + 0] * w[i].x + xs[j * 4 + 1] * w[i].y
                     + xs[j * 4 + 2] * w[i].z + xs[j * 4 + 3] * w[i].w;
            }
        }
#pragma unroll
        for (int o = 16; o; o >>= 1) acc += __shfl_xor_sync(0xffffffffu, acc, o);
        if (lane == 0) {
            float* dst = (mat == 0) ? g_q : ((mat == 1) ? g_k : g_v);
            dst[row] = acc;
        }
    }
    __threadfence();                 // publish q/k/v (release)
    __syncthreads();
    if (tid == 0) atomicAdd(&g_qkv_cnt, 1u);

    int ci = *ci_p;

    // ---- Phase B: stream copy of keys (ci, MAX) — no q dependency ----
    {
        size_t start  = ((size_t)ci + 1) * (D_MODEL / 4);
        size_t end    = (size_t)MAX_SEQ_LEN * (D_MODEL / 4);
        size_t stride = (size_t)NBLK * 256;
        size_t i = start + (size_t)bid * 256 + tid;
        for (; i + stride < end; i += 2 * stride) {
            float4 a0 = __ldcs(pk + i), b0 = __ldcs(pv + i);
            float4 a1 = __ldcs(pk + i + stride), b1 = __ldcs(pv + i + stride);
            __stcs(ok + i, a0); __stcs(ov + i, b0);
            __stcs(ok + i + stride, a1); __stcs(ov + i + stride, b1);
        }
        for (; i < end; i += stride) {
            __stcs(ok + i, __ldcs(pk + i));
            __stcs(ov + i, __ldcs(pv + i));
        }
    }

    // ---- acquire barrier 1: all blocks resident => no deadlock ----
    if (tid == 0) {
        while (*(volatile unsigned*)&g_qkv_cnt < NBLK) __nanosleep(64);
    }
    __syncthreads();
    __threadfence();

    // ---- Phase C: lower-half copy + flash attention ----
    int h  = bid / KB2;
    int kb = bid % KB2;
    int nkeys = ci + 1;                       // includes new key row
    int chunk = (nkeys + KB2 - 1) / KB2;
    int lo = kb * chunk;
    int hi = min(lo + chunk, nkeys);

    float4 q     = ((const float4*)(g_q + h * HEAD_DIM))[lane];
    float4 foldk = ((const float4*)(g_k + h * HEAD_DIM))[lane];
    float4 foldv = ((const float4*)(g_v + h * HEAD_DIM))[lane];

    float m = -INFINITY, l = 0.f;
    float4 acc = make_float4(0.f, 0.f, 0.f, 0.f);
    const int seg_stride = D_MODEL / 4;
    const int hbase = h * (HEAD_DIM / 4) + lane;

    for (int keyA = lo + wid; keyA < hi; keyA += 16) {
        int keyB = keyA + 8;
        bool pb = keyB < hi;
        size_t ia = (size_t)keyA * seg_stride + hbase;
        size_t ib = (size_t)keyB * seg_stride + hbase;

        float4 kA, vA;
        if (keyA == ci) { kA = foldk; vA = foldv; }
        else            { kA = __ldcs(pk + ia); vA = __ldcs(pv + ia); }
        float4 kB = foldk, vB = foldv;
        if (pb && keyB != ci) { kB = __ldcs(pk + ib); vB = __ldcs(pv + ib); }

        __stcs(ok + ia, kA); __stcs(ov + ia, vA);
        if (pb) { __stcs(ok + ib, kB); __stcs(ov + ib, vB); }

        bool aval = keyA < ci;
        bool bval = pb && keyB < ci;
        float sA = kA.x * q.x + kA.y * q.y + kA.z * q.z + kA.w * q.w;
        float sB = kB.x * q.x + kB.y * q.y + kB.z * q.z + kB.w * q.w;
#pragma unroll
        for (int o = 16; o; o >>= 1) {
            sA += __shfl_xor_sync(0xffffffffu, sA, o);
            sB += __shfl_xor_sync(0xffffffffu, sB, o);
        }
        sA = aval ? sA * SCALE : -INFINITY;
        sB = bval ? sB * SCALE : -INFINITY;
        float mn = fmaxf(m, fmaxf(sA, sB));
        if (mn != -INFINITY) {
            float corr = __expf(m - mn);
            float pA   = __expf(sA - mn);
            float pB   = __expf(sB - mn);
            acc.x = acc.x * corr + pA * vA.x + pB * vB.x;
            acc.y = acc.y * corr + pA * vA.y + pB * vB.y;
            acc.z = acc.z * corr + pA * vA.z + pB * vB.z;
            acc.w = acc.w * corr + pA * vA.w + pB * vB.w;
            l = l * corr + pA + pB;
            m = mn;
        }
    }

    wacc[wid][lane * 4 + 0] = acc.x;
    wacc[wid][lane * 4 + 1] = acc.y;
    wacc[wid][lane * 4 + 2] = acc.z;
    wacc[wid][lane * 4 + 3] = acc.w;
    if (lane == 0) { wm[wid] = m; wl[wid] = l; }
    __syncthreads();

    if (tid < HEAD_DIM) {
        float mb = -INFINITY;
#pragma unroll
        for (int w = 0; w < 8; w++) mb = fmaxf(mb, wm[w]);
        float lb = 0.f, od = 0.f;
        if (mb != -INFINITY) {
#pragma unroll
            for (int w = 0; w < 8; w++) {
                float e = __expf(wm[w] - mb);
                lb += wl[w] * e;
                od += wacc[w][tid] * e;
            }
        }
        int idx = h * KB2 + kb;
        g_pacc[idx * HEAD_DIM + tid] = od;
        if (tid == 0) { g_pm[idx] = mb; g_pl[idx] = lb; }
    }
    __syncthreads();

    // ---- per-head last-block reduce ----
    if (tid == 0) {
        __threadfence();
        unsigned old = atomicAdd(&g_sem[h], 1u);
        is_last = (old == KB2 - 1);
        if (is_last) g_sem[h] = 0;            // self-reset for next replay
    }
    __syncthreads();

    if (is_last) {
        __threadfence();
        float* red = wacc[0];
        if (tid < HEAD_DIM) red[tid] = g_q[h * HEAD_DIM + tid] * g_k[h * HEAD_DIM + tid];
        __syncthreads();
        for (int s = 64; s; s >>= 1) {
            if (tid < s) red[tid] += red[tid + s];
            __syncthreads();
        }
        float s_new = red[0] * SCALE;         // new key always valid

        if (tid < HEAD_DIM) {
            float mg = s_new;
            for (int sp = 0; sp < KB2; sp++) mg = fmaxf(mg, g_pm[h * KB2 + sp]);
            float en  = __expf(s_new - mg);
            float num = en * g_v[h * HEAD_DIM + tid];
            float den = en;
            for (int sp = 0; sp < KB2; sp++) {
                float e = __expf(g_pm[h * KB2 + sp] - mg);
                num += e * g_pacc[(h * KB2 + sp) * HEAD_DIM + tid];
                den += e * g_pl[h * KB2 + sp];
            }
            g_attn[h * HEAD_DIM + tid] = num / den;
        }
        __syncthreads();
        if (tid == 0) {
            __threadfence();                  // publish g_attn
            atomicAdd(&g_attn_cnt, 1u);
        }
    }

    // ---- acquire barrier 2: wait for all 16 heads' outputs ----
    if (tid == 0) {
        while (*(volatile unsigned*)&g_attn_cnt < NUM_HEADS) __nanosleep(64);
    }
    __syncthreads();
    __threadfence();

    // ---- Phase D: output projection y = attn @ Wo.T ----
    {
        float4* xs4 = (float4*)xs;            // reuse smem (x no longer needed)
        const float4* a4 = (const float4*)g_attn;
#pragma unroll
        for (int i = 0; i < 2; i++) xs4[tid + i * 256] = a4[tid + i * 256];
    }
    __syncthreads();

    int sub = tid & 127;
    for (int row = bid * 2 + (tid >> 7); row < D_MODEL; row += NBLK * 2) {
        const float4* wr = (const float4*)(Wo + (size_t)row * D_MODEL);
        float4 w[4];
#pragma unroll
        for (int it = 0; it < 4; it++) w[it] = __ldcs(wr + sub + it * 128);
        float acc2 = 0.f;
#pragma unroll
        for (int it = 0; it < 4; it++) {
            int j = sub + it * 128;
            acc2 += xs[j * 4 + 0] * w[it].x + xs[j * 4 + 1] * w[it].y
                  + xs[j * 4 + 2] * w[it].z + xs[j * 4 + 3] * w[it].w;
        }
#pragma unroll
        for (int o = 16; o; o >>= 1) acc2 += __shfl_xor_sync(0xffffffffu, acc2, o);
        if (lane == 0) wm[tid >> 5] = acc2;   // reuse wm as 8-slot partial buf
        __syncthreads();
        if (sub == 0) {
            int p = (tid >> 5);
            y[row] = wm[p] + wm[p + 1] + wm[p + 2] + wm[p + 3];
        }
        __syncthreads();
    }

    // ---- cleanup: last block to finish resets the spin counters ----
    if (tid == 0) {
        unsigned old = atomicAdd(&g_done_cnt, 1u);
        if (old == NBLK - 1) {                // everyone is past both spins
            g_qkv_cnt = 0;
            g_attn_cnt = 0;
            g_done_cnt = 0;
        }
    }
}

// ---------------- launch ---------------------------------------------------
extern "C" void kernel_launch(void* const* d_in, const int* in_sizes, int n_in,
                              void* d_out, int out_size) {
    const float* x  = (const float*)d_in[0];
    const float* Wq = (const float*)d_in[1];
    const float* Wk = (const float*)d_in[2];
    const float* Wv = (const float*)d_in[3];
    const float* Wo = (const float*)d_in[4];
    const float* pk = (const float*)d_in[5];
    const float* pv = (const float*)d_in[6];
    const int*   ci = (const int*)d_in[7];

    float* y  = (float*)d_out;
    float* ok = y + D_MODEL;
    float* ov = ok + (size_t)MAX_SEQ_LEN * D_MODEL;

    mega_kernel<<<NBLK, 256>>>(x, Wq, Wk, Wv, Wo,
                               (const float4*)pk, (const float4*)pv,
                               (float4*)ok, (float4*)ov, ci, y);
}